// round 4
// baseline (speedup 1.0000x reference)
#include <cuda_runtime.h>
#include <cuda_fp16.h>
#include <math.h>

// ---------------- problem constants ----------------
#define BS    32
#define LQ    300
#define NH    8
#define HD    32
#define EMB   (NH*HD)        // 256
#define NLVL  4
#define NPTS  4
#define SUMP  (NLVL*NPTS)    // 16
#define TOTAL 8500
#define MROWS (BS*LQ)        // 9600
#define NPOINT ((size_t)BS*NH*LQ*SUMP)   // 1,228,800

__device__ __constant__ int c_lvl_start[NLVL] = {0, 6400, 8000, 8400};
__device__ __constant__ int c_lvl_H[NLVL]     = {80, 40, 20, 10};
__device__ __constant__ int c_lvl_W[NLVL]     = {80, 40, 20, 10};

// ---------------- scratch ----------------
__device__ __half g_valueT[(size_t)BS*NH*TOTAL*HD];    // ~139 MB, [b,h,s,d] fp16
__device__ float  g_attn[(size_t)MROWS*NH*SUMP];       // linear: gm*128 + (h*16+p)
__device__ float  g_loc[(size_t)MROWS*NH*SUMP*2];      // linear: gm*256 + (h*32+p*2+comp)
__device__ int4   g_midx[NPOINT];                      // [bh][q][p]: 4 clamped tap indices
__device__ float4 g_mw[NPOINT];                        // [bh][q][p]: 4 attn-premult weights

// ---------------- f32x2 packed helpers (sm_103a) ----------------
typedef unsigned long long ull;
__device__ __forceinline__ ull pack2(float lo, float hi) {
    ull r; asm("mov.b64 %0, {%1, %2};" : "=l"(r) : "f"(lo), "f"(hi)); return r;
}
__device__ __forceinline__ void unpack2(ull v, float& lo, float& hi) {
    asm("mov.b64 {%0, %1}, %2;" : "=f"(lo), "=f"(hi) : "l"(v));
}
__device__ __forceinline__ void ffma2(ull& d, ull a, ull b) {
    asm("fma.rn.f32x2 %0, %1, %2, %0;" : "+l"(d) : "l"(a), "l"(b));
}

// ================= kernel 1: value transpose fp32 [b,h,d,s] -> fp16 [b,h,s,d] =================
__global__ __launch_bounds__(256) void k_transpose(const float* __restrict__ value) {
    __shared__ float tile[32 * 68];
    int bh = blockIdx.y;
    int s0 = blockIdx.x * 64;
    int t  = threadIdx.x;
    int sx4 = t & 15;
    int dh  = t >> 4;

    const float* src = value + (size_t)bh * HD * TOTAL;
    __half* dst = g_valueT + (size_t)bh * TOTAL * HD;

    int sbase = s0 + sx4 * 4;
    #pragma unroll
    for (int i = 0; i < 2; i++) {
        int d = dh + i * 16;
        float4 v;
        if (sbase + 3 < TOTAL) {
            v = *(const float4*)(src + (size_t)d * TOTAL + sbase);
        } else {
            v.x = (sbase + 0 < TOTAL) ? src[(size_t)d * TOTAL + sbase + 0] : 0.f;
            v.y = (sbase + 1 < TOTAL) ? src[(size_t)d * TOTAL + sbase + 1] : 0.f;
            v.z = (sbase + 2 < TOTAL) ? src[(size_t)d * TOTAL + sbase + 2] : 0.f;
            v.w = (sbase + 3 < TOTAL) ? src[(size_t)d * TOTAL + sbase + 3] : 0.f;
        }
        *(float4*)(tile + d * 68 + sx4 * 4) = v;
    }
    __syncthreads();
    #pragma unroll
    for (int i = 0; i < 4; i++) {
        int e  = t + i * 256;
        int r  = e >> 4;
        int dp = e & 15;
        int s  = s0 + r;
        if (s < TOTAL) {
            float lo = tile[(2*dp)     * 68 + r];
            float hi = tile[(2*dp + 1) * 68 + r];
            *((__half2*)(dst + (size_t)s * HD) + dp) = __floats2half2_rn(lo, hi);
        }
    }
}

// ================= kernel 2: projections + softmax + locations =================
__global__ __launch_bounds__(192) void k_proj(const float* __restrict__ query,
                                              const float* __restrict__ refpts,
                                              const float* __restrict__ W_off,
                                              const float* __restrict__ b_off,
                                              const float* __restrict__ W_attn,
                                              const float* __restrict__ b_attn) {
    __shared__ float qs[EMB * 34];       // [k][row]
    int m0 = blockIdx.x * 32;
    int t  = threadIdx.x;

    for (int idx = t; idx < 32 * EMB; idx += 192) {
        int row = idx >> 8;
        int k   = idx & 255;
        qs[k * 34 + row] = query[(size_t)m0 * EMB + idx];
    }
    __syncthreads();

    int rg   = t / 48;
    int cg   = t % 48;
    int col0 = cg * 8;
    bool is_off = (col0 < EMB);
    const float* Wp = is_off ? (W_off + col0) : (W_attn + (col0 - EMB));
    int ld = is_off ? EMB : (NH * SUMP);

    ull acc[4][8];
    #pragma unroll
    for (int j = 0; j < 4; j++)
        #pragma unroll
        for (int c = 0; c < 8; c++) acc[j][c] = 0ull;

    #pragma unroll 2
    for (int k = 0; k < EMB; k++) {
        ull q2[4];
        #pragma unroll
        for (int j = 0; j < 4; j++)
            q2[j] = *(const ull*)(qs + k * 34 + rg * 8 + 2 * j);
        float4 w0 = *(const float4*)(Wp + (size_t)k * ld);
        float4 w1 = *(const float4*)(Wp + (size_t)k * ld + 4);
        float w[8] = {w0.x, w0.y, w0.z, w0.w, w1.x, w1.y, w1.z, w1.w};
        #pragma unroll
        for (int c = 0; c < 8; c++) {
            ull w2 = pack2(w[c], w[c]);
            #pragma unroll
            for (int j = 0; j < 4; j++)
                ffma2(acc[j][c], q2[j], w2);
        }
    }

    float bias[8];
    {
        const float* bp = is_off ? (b_off + col0) : (b_attn + (col0 - EMB));
        #pragma unroll
        for (int c = 0; c < 8; c++) bias[c] = bp[c];
    }

    if (is_off) {
        #pragma unroll
        for (int j = 0; j < 4; j++) {
            #pragma unroll
            for (int par = 0; par < 2; par++) {
                int r  = rg * 8 + 2 * j + par;
                int gm = m0 + r;
                float4 rp = *(const float4*)(refpts + (size_t)gm * 4);
                float ov[8];
                #pragma unroll
                for (int c = 0; c < 8; c++) {
                    float lo, hi; unpack2(acc[j][c], lo, hi);
                    float v = (par ? hi : lo) + bias[c];
                    int comp = (col0 + c) & 1;
                    float rxy = comp ? rp.y : rp.x;
                    float rwh = comp ? rp.w : rp.z;
                    ov[c] = fmaf(v * 0.125f, rwh, rxy);
                }
                *(float4*)(g_loc + (size_t)gm * 256 + col0)     = make_float4(ov[0], ov[1], ov[2], ov[3]);
                *(float4*)(g_loc + (size_t)gm * 256 + col0 + 4) = make_float4(ov[4], ov[5], ov[6], ov[7]);
            }
        }
    } else {
        int hidx = col0 - EMB;
        unsigned mask16 = 0xFFFFu << (t & 16);
        #pragma unroll
        for (int j = 0; j < 4; j++) {
            #pragma unroll
            for (int par = 0; par < 2; par++) {
                int r  = rg * 8 + 2 * j + par;
                int gm = m0 + r;
                float v[8];
                float mx = -1e30f;
                #pragma unroll
                for (int c = 0; c < 8; c++) {
                    float lo, hi; unpack2(acc[j][c], lo, hi);
                    v[c] = (par ? hi : lo) + bias[c];
                    mx = fmaxf(mx, v[c]);
                }
                mx = fmaxf(mx, __shfl_xor_sync(mask16, mx, 1));
                float s = 0.f;
                #pragma unroll
                for (int c = 0; c < 8; c++) { v[c] = __expf(v[c] - mx); s += v[c]; }
                s += __shfl_xor_sync(mask16, s, 1);
                float inv = __frcp_rn(s);
                *(float4*)(g_attn + (size_t)gm * 128 + hidx)     = make_float4(v[0]*inv, v[1]*inv, v[2]*inv, v[3]*inv);
                *(float4*)(g_attn + (size_t)gm * 128 + hidx + 4) = make_float4(v[4]*inv, v[5]*inv, v[6]*inv, v[7]*inv);
            }
        }
    }
}

// ================= kernel 2.5: tap meta (indices + attn-premult weights) =================
// 1 thread per (bh, q, p). Writes [bh][q][p] layout.
__global__ __launch_bounds__(256) void k_meta() {
    int e = blockIdx.x * 256 + threadIdx.x;   // < NPOINT
    int p   = e & 15;
    int bhq = e >> 4;            // bh*LQ + q
    int q   = bhq % LQ;
    int bh  = bhq / LQ;
    int b   = bh >> 3;
    int h   = bh & 7;
    int gm  = b * LQ + q;

    float lx = g_loc[(size_t)gm * 256 + h * 32 + 2 * p];
    float ly = g_loc[(size_t)gm * 256 + h * 32 + 2 * p + 1];
    float a  = g_attn[(size_t)gm * 128 + h * 16 + p];

    int lvl = p >> 2;
    int Hh = c_lvl_H[lvl], Ww = c_lvl_W[lvl];
    int st = c_lvl_start[lvl];

    float x = lx * (float)Ww - 0.5f;
    float y = ly * (float)Hh - 0.5f;
    float fx0 = floorf(x), fy0 = floorf(y);
    int ix0 = (int)fx0, iy0 = (int)fy0;
    float fx = x - fx0, fy = y - fy0;
    int ix1 = ix0 + 1, iy1 = iy0 + 1;

    bool vx0 = (ix0 >= 0) & (ix0 < Ww);
    bool vx1 = (ix1 >= 0) & (ix1 < Ww);
    bool vy0 = (iy0 >= 0) & (iy0 < Hh);
    bool vy1 = (iy1 >= 0) & (iy1 < Hh);

    int cx0 = min(max(ix0, 0), Ww - 1);
    int cx1 = min(max(ix1, 0), Ww - 1);
    int cy0 = min(max(iy0, 0), Hh - 1);
    int cy1 = min(max(iy1, 0), Hh - 1);

    int4 idx;
    idx.x = st + cy0 * Ww + cx0;
    idx.y = st + cy0 * Ww + cx1;
    idx.z = st + cy1 * Ww + cx0;
    idx.w = st + cy1 * Ww + cx1;

    float4 w;
    w.x = (vx0 & vy0) ? a * (1.f - fx) * (1.f - fy) : 0.f;
    w.y = (vx1 & vy0) ? a * fx * (1.f - fy)         : 0.f;
    w.z = (vx0 & vy1) ? a * (1.f - fx) * fy         : 0.f;
    w.w = (vx1 & vy1) ? a * fx * fy                 : 0.f;

    g_midx[e] = idx;
    g_mw[e]   = w;
}

// ================= kernel 3: bilinear sampling + weighted sum =================
// Warp = 2 queries (half-warp each); lane = channel pair (half2 taps, f32x2 math).
#define QPAIRS (LQ/2)   // 150
__global__ __launch_bounds__(256) void k_sample(float* __restrict__ out) {
    int warp = blockIdx.x * 8 + (threadIdx.x >> 5);
    if (warp >= BS * NH * QPAIRS) return;
    int lane = threadIdx.x & 31;
    int half = lane >> 4;
    int l    = lane & 15;

    int qp = warp % QPAIRS;
    int bh = warp / QPAIRS;
    int q  = qp * 2 + half;
    int b  = bh >> 3;
    int h  = bh & 7;
    int gm = b * LQ + q;

    const __half2* __restrict__ vt2 =
        (const __half2*)(g_valueT + (size_t)bh * TOTAL * HD);
    const int4*   __restrict__ mi = g_midx + ((size_t)bh * LQ + q) * SUMP;
    const float4* __restrict__ mw = g_mw   + ((size_t)bh * LQ + q) * SUMP;

    ull acc2 = 0ull;
    #pragma unroll
    for (int p = 0; p < SUMP; p++) {
        int4   id = __ldg(mi + p);
        float4 w  = __ldg(mw + p);

        __half2 h00 = __ldg(vt2 + (size_t)id.x * 16 + l);
        __half2 h10 = __ldg(vt2 + (size_t)id.y * 16 + l);
        __half2 h01 = __ldg(vt2 + (size_t)id.z * 16 + l);
        __half2 h11 = __ldg(vt2 + (size_t)id.w * 16 + l);

        float2 f00 = __half22float2(h00);
        float2 f10 = __half22float2(h10);
        float2 f01 = __half22float2(h01);
        float2 f11 = __half22float2(h11);

        ffma2(acc2, pack2(f00.x, f00.y), pack2(w.x, w.x));
        ffma2(acc2, pack2(f10.x, f10.y), pack2(w.y, w.y));
        ffma2(acc2, pack2(f01.x, f01.y), pack2(w.z, w.z));
        ffma2(acc2, pack2(f11.x, f11.y), pack2(w.w, w.w));
    }
    float lo, hi; unpack2(acc2, lo, hi);
    *(float2*)(out + (size_t)gm * EMB + h * HD + 2 * l) = make_float2(lo, hi);
}

// ================= launch =================
extern "C" void kernel_launch(void* const* d_in, const int* in_sizes, int n_in,
                              void* d_out, int out_size) {
    const float* query  = (const float*)d_in[0];
    const float* refpts = (const float*)d_in[1];
    const float* value  = (const float*)d_in[2];
    const float* W_off  = (const float*)d_in[4];
    const float* b_off  = (const float*)d_in[5];
    const float* W_attn = (const float*)d_in[6];
    const float* b_attn = (const float*)d_in[7];
    float* out = (float*)d_out;

    dim3 tgrid((TOTAL + 63) / 64, BS * NH);
    k_transpose<<<tgrid, 256>>>(value);

    k_proj<<<MROWS / 32, 192>>>(query, refpts, W_off, b_off, W_attn, b_attn);

    k_meta<<<(int)(NPOINT / 256), 256>>>();

    int nwarps = BS * NH * QPAIRS;            // 38400
    k_sample<<<(nwarps + 7) / 8, 256>>>(out);
}

// round 5
// speedup vs baseline: 1.2658x; 1.2658x over previous
#include <cuda_runtime.h>
#include <cuda_fp16.h>
#include <math.h>

// ---------------- problem constants ----------------
#define BS    32
#define LQ    300
#define NH    8
#define HD    32
#define EMB   (NH*HD)        // 256
#define NLVL  4
#define NPTS  4
#define SUMP  (NLVL*NPTS)    // 16
#define TOTAL 8500
#define MROWS (BS*LQ)        // 9600
#define NPOINT ((size_t)BS*NH*LQ*SUMP)   // 1,228,800

__device__ __constant__ int c_lvl_start[NLVL] = {0, 6400, 8000, 8400};
__device__ __constant__ int c_lvl_H[NLVL]     = {80, 40, 20, 10};
__device__ __constant__ int c_lvl_W[NLVL]     = {80, 40, 20, 10};

// ---------------- scratch ----------------
__device__ __half g_valueT[(size_t)BS*NH*TOTAL*HD];  // ~139 MB, [b,h,s,d] fp16
__device__ float  g_attn[NPOINT];                    // [bh][q][p] softmaxed weights
__device__ int4   g_midx[NPOINT];                    // [bh][q][p] 4 clamped tap indices
__device__ float4 g_mw[NPOINT];                      // [bh][q][p] 4 bilinear weights (not attn-premult)

// ---------------- f32x2 packed helpers (sm_103a) ----------------
typedef unsigned long long ull;
__device__ __forceinline__ ull pack2(float lo, float hi) {
    ull r; asm("mov.b64 %0, {%1, %2};" : "=l"(r) : "f"(lo), "f"(hi)); return r;
}
__device__ __forceinline__ void unpack2(ull v, float& lo, float& hi) {
    asm("mov.b64 {%0, %1}, %2;" : "=f"(lo), "=f"(hi) : "l"(v));
}
__device__ __forceinline__ void ffma2(ull& d, ull a, ull b) {
    asm("fma.rn.f32x2 %0, %1, %2, %0;" : "+l"(d) : "l"(a), "l"(b));
}

// ================= kernel 1: value transpose fp32 [b,h,d,s] -> fp16 [b,h,s,d] =================
__global__ __launch_bounds__(256) void k_transpose(const float* __restrict__ value) {
    __shared__ float tile[32 * 68];
    int bh = blockIdx.y;
    int s0 = blockIdx.x * 64;
    int t  = threadIdx.x;
    int sx4 = t & 15;
    int dh  = t >> 4;

    const float* src = value + (size_t)bh * HD * TOTAL;
    __half* dst = g_valueT + (size_t)bh * TOTAL * HD;

    int sbase = s0 + sx4 * 4;
    #pragma unroll
    for (int i = 0; i < 2; i++) {
        int d = dh + i * 16;
        float4 v;
        if (sbase + 3 < TOTAL) {
            v = *(const float4*)(src + (size_t)d * TOTAL + sbase);
        } else {
            v.x = (sbase + 0 < TOTAL) ? src[(size_t)d * TOTAL + sbase + 0] : 0.f;
            v.y = (sbase + 1 < TOTAL) ? src[(size_t)d * TOTAL + sbase + 1] : 0.f;
            v.z = (sbase + 2 < TOTAL) ? src[(size_t)d * TOTAL + sbase + 2] : 0.f;
            v.w = (sbase + 3 < TOTAL) ? src[(size_t)d * TOTAL + sbase + 3] : 0.f;
        }
        *(float4*)(tile + d * 68 + sx4 * 4) = v;
    }
    __syncthreads();
    #pragma unroll
    for (int i = 0; i < 4; i++) {
        int e  = t + i * 256;
        int r  = e >> 4;
        int dp = e & 15;
        int s  = s0 + r;
        if (s < TOTAL) {
            float lo = tile[(2*dp)     * 68 + r];
            float hi = tile[(2*dp + 1) * 68 + r];
            *((__half2*)(dst + (size_t)s * HD) + dp) = __floats2half2_rn(lo, hi);
        }
    }
}

// ================= kernel 2: fused projections + softmax + tap meta =================
// Block = 32 query rows, 384 threads. Thread: rt = t/96 -> rows rt*8..+7 (4 f32x2 pairs),
// ct = t%96 -> cols 4ct..4ct+3 of the virtual [W_off | W_attn] 384-col matrix.
// Each warp is uniform: warps {0,1},{3,4},{6,7},{9,10} = off; warps {2,5,8,11} = attn.
__global__ __launch_bounds__(384, 2) void k_proj(const float* __restrict__ query,
                                                 const float* __restrict__ refpts,
                                                 const float* __restrict__ W_off,
                                                 const float* __restrict__ b_off,
                                                 const float* __restrict__ W_attn,
                                                 const float* __restrict__ b_attn) {
    __shared__ float qs[EMB * 34];       // [k][row], stride 34 (8B aligned)
    int m0 = blockIdx.x * 32;
    int t  = threadIdx.x;

    for (int idx = t; idx < 32 * EMB; idx += 384) {
        int row = idx >> 8;
        int k   = idx & 255;
        qs[k * 34 + row] = query[(size_t)m0 * EMB + idx];
    }
    __syncthreads();

    int rt = t / 96;                     // 0..3
    int ct = t % 96;                     // 0..95
    bool is_off = (ct < 64);

    const float* Wp;
    int ldw;
    if (is_off) { Wp = W_off  + 4 * ct;        ldw = EMB; }
    else        { Wp = W_attn + 4 * (ct - 64); ldw = NH * SUMP; }

    ull acc[4][4];
    #pragma unroll
    for (int j = 0; j < 4; j++)
        #pragma unroll
        for (int c = 0; c < 4; c++) acc[j][c] = 0ull;

    #pragma unroll 2
    for (int k = 0; k < EMB; k++) {
        ull q2[4];
        #pragma unroll
        for (int j = 0; j < 4; j++)
            q2[j] = *(const ull*)(qs + k * 34 + rt * 8 + 2 * j);
        float4 w = *(const float4*)(Wp + (size_t)k * ldw);
        ull w2[4];
        w2[0] = pack2(w.x, w.x); w2[1] = pack2(w.y, w.y);
        w2[2] = pack2(w.z, w.z); w2[3] = pack2(w.w, w.w);
        #pragma unroll
        for (int c = 0; c < 4; c++)
            #pragma unroll
            for (int j = 0; j < 4; j++)
                ffma2(acc[j][c], q2[j], w2[c]);
    }

    float bias_[4];
    {
        const float* bp = is_off ? (b_off + 4 * ct) : (b_attn + 4 * (ct - 64));
        float4 bb = *(const float4*)bp;
        bias_[0] = bb.x; bias_[1] = bb.y; bias_[2] = bb.z; bias_[3] = bb.w;
    }

    if (is_off) {
        // cols 4ct..4ct+3 = points (pbase, pbase+1) x (comp x, comp y)
        int h     = ct >> 3;
        int pbase = (2 * ct) & 15;
        int lvl   = pbase >> 2;          // both points share a level (pbase even)
        int Hh = c_lvl_H[lvl], Ww = c_lvl_W[lvl];
        int st = c_lvl_start[lvl];

        #pragma unroll
        for (int j = 0; j < 4; j++) {
            #pragma unroll
            for (int par = 0; par < 2; par++) {
                int r  = rt * 8 + 2 * j + par;
                int gm = m0 + r;
                int b  = gm / LQ;
                int q  = gm - b * LQ;
                float4 rp = __ldg((const float4*)refpts + gm);
                size_t obase = ((size_t)(b * NH + h) * LQ + q) * SUMP + pbase;
                #pragma unroll
                for (int pt = 0; pt < 2; pt++) {
                    float lo0, hi0, lo1, hi1;
                    unpack2(acc[j][2*pt],     lo0, hi0);
                    unpack2(acc[j][2*pt + 1], lo1, hi1);
                    float vx = (par ? hi0 : lo0) + bias_[2*pt];
                    float vy = (par ? hi1 : lo1) + bias_[2*pt + 1];
                    float locx = fmaf(vx * 0.125f, rp.z, rp.x);   // (1/NPTS)*0.5
                    float locy = fmaf(vy * 0.125f, rp.w, rp.y);

                    float x = locx * (float)Ww - 0.5f;
                    float y = locy * (float)Hh - 0.5f;
                    float fx0 = floorf(x), fy0 = floorf(y);
                    int ix0 = (int)fx0, iy0 = (int)fy0;
                    float fx = x - fx0, fy = y - fy0;
                    int ix1 = ix0 + 1, iy1 = iy0 + 1;

                    bool vx0 = (ix0 >= 0) & (ix0 < Ww);
                    bool vx1 = (ix1 >= 0) & (ix1 < Ww);
                    bool vy0 = (iy0 >= 0) & (iy0 < Hh);
                    bool vy1 = (iy1 >= 0) & (iy1 < Hh);

                    int cx0 = min(max(ix0, 0), Ww - 1);
                    int cx1 = min(max(ix1, 0), Ww - 1);
                    int cy0 = min(max(iy0, 0), Hh - 1);
                    int cy1 = min(max(iy1, 0), Hh - 1);

                    int4 idx;
                    idx.x = st + cy0 * Ww + cx0;
                    idx.y = st + cy0 * Ww + cx1;
                    idx.z = st + cy1 * Ww + cx0;
                    idx.w = st + cy1 * Ww + cx1;

                    float4 w4;
                    w4.x = (vx0 & vy0) ? (1.f - fx) * (1.f - fy) : 0.f;
                    w4.y = (vx1 & vy0) ? fx * (1.f - fy)         : 0.f;
                    w4.z = (vx0 & vy1) ? (1.f - fx) * fy         : 0.f;
                    w4.w = (vx1 & vy1) ? fx * fy                 : 0.f;

                    g_midx[obase + pt] = idx;
                    g_mw[obase + pt]   = w4;
                }
            }
        }
    } else {
        // cols (ct-64)*4 of attn: h = (ct-64)>>2, p0 = (4*(ct-64))&15
        int cta = ct - 64;
        int h   = cta >> 2;
        int p0  = (4 * cta) & 15;
        #pragma unroll
        for (int j = 0; j < 4; j++) {
            #pragma unroll
            for (int par = 0; par < 2; par++) {
                int r  = rt * 8 + 2 * j + par;
                int gm = m0 + r;
                int b  = gm / LQ;
                int q  = gm - b * LQ;
                float v[4];
                float mx = -1e30f;
                #pragma unroll
                for (int c = 0; c < 4; c++) {
                    float lo, hi; unpack2(acc[j][c], lo, hi);
                    v[c] = (par ? hi : lo) + bias_[c];
                    mx = fmaxf(mx, v[c]);
                }
                mx = fmaxf(mx, __shfl_xor_sync(0xffffffffu, mx, 1));
                mx = fmaxf(mx, __shfl_xor_sync(0xffffffffu, mx, 2));
                float s = 0.f;
                #pragma unroll
                for (int c = 0; c < 4; c++) { v[c] = __expf(v[c] - mx); s += v[c]; }
                s += __shfl_xor_sync(0xffffffffu, s, 1);
                s += __shfl_xor_sync(0xffffffffu, s, 2);
                float inv = __frcp_rn(s);
                size_t obase = ((size_t)(b * NH + h) * LQ + q) * SUMP + p0;
                *(float4*)(g_attn + obase) =
                    make_float4(v[0]*inv, v[1]*inv, v[2]*inv, v[3]*inv);
            }
        }
    }
}

// ================= kernel 3: bilinear sampling + weighted sum =================
// Warp = 4 queries; 8 lanes per query; lane = 4 channels (LDG.64 taps, HFMA2 bilinear).
#define QQUADS (LQ/4)   // 75
__global__ __launch_bounds__(256) void k_sample(float* __restrict__ out) {
    int wq = blockIdx.x * 8 + (threadIdx.x >> 5);   // < 19200
    int lane = threadIdx.x & 31;
    int g = lane >> 3;        // q sub-index in quad
    int l = lane & 7;         // channel quad index (channels 4l..4l+3)

    int quad = wq % QQUADS;
    int bh   = wq / QQUADS;
    int q    = quad * 4 + g;
    int b    = bh >> 3;
    int h    = bh & 7;

    size_t base = ((size_t)bh * LQ + q) * SUMP;
    const int4*   __restrict__ mi = g_midx + base;
    const float4* __restrict__ mw = g_mw   + base;
    const float*  __restrict__ at = g_attn + base;

    float a0 = __ldg(at + l);
    float a1 = __ldg(at + l + 8);

    const ull* __restrict__ vt8 =
        (const ull*)(g_valueT + (size_t)bh * TOTAL * HD);   // 8B = 4 channels

    const unsigned FULL = 0xffffffffu;
    ull accA = 0ull, accB = 0ull;

    #pragma unroll
    for (int p = 0; p < SUMP; p++) {
        int4   id = __ldg(mi + p);
        float4 w  = __ldg(mw + p);
        float  a  = __shfl_sync(FULL, (p < 8) ? a0 : a1, (lane & 24) | (p & 7));

        __half2 bl0 = __float2half2_rn(0.f);
        __half2 bl1 = __float2half2_rn(0.f);

        {
            ull v = __ldg(vt8 + (size_t)id.x * 8 + l);
            __half2 vlo, vhi;
            asm("mov.b64 {%0, %1}, %2;" : "=r"(*(unsigned*)&vlo), "=r"(*(unsigned*)&vhi) : "l"(v));
            __half2 wh = __float2half2_rn(w.x);
            bl0 = __hfma2(vlo, wh, bl0); bl1 = __hfma2(vhi, wh, bl1);
        }
        {
            ull v = __ldg(vt8 + (size_t)id.y * 8 + l);
            __half2 vlo, vhi;
            asm("mov.b64 {%0, %1}, %2;" : "=r"(*(unsigned*)&vlo), "=r"(*(unsigned*)&vhi) : "l"(v));
            __half2 wh = __float2half2_rn(w.y);
            bl0 = __hfma2(vlo, wh, bl0); bl1 = __hfma2(vhi, wh, bl1);
        }
        {
            ull v = __ldg(vt8 + (size_t)id.z * 8 + l);
            __half2 vlo, vhi;
            asm("mov.b64 {%0, %1}, %2;" : "=r"(*(unsigned*)&vlo), "=r"(*(unsigned*)&vhi) : "l"(v));
            __half2 wh = __float2half2_rn(w.z);
            bl0 = __hfma2(vlo, wh, bl0); bl1 = __hfma2(vhi, wh, bl1);
        }
        {
            ull v = __ldg(vt8 + (size_t)id.w * 8 + l);
            __half2 vlo, vhi;
            asm("mov.b64 {%0, %1}, %2;" : "=r"(*(unsigned*)&vlo), "=r"(*(unsigned*)&vhi) : "l"(v));
            __half2 wh = __float2half2_rn(w.w);
            bl0 = __hfma2(vlo, wh, bl0); bl1 = __hfma2(vhi, wh, bl1);
        }

        float2 f0 = __half22float2(bl0);
        float2 f1 = __half22float2(bl1);
        ull a2 = pack2(a, a);
        ffma2(accA, pack2(f0.x, f0.y), a2);
        ffma2(accB, pack2(f1.x, f1.y), a2);
    }

    float c0, c1, c2, c3;
    unpack2(accA, c0, c1);
    unpack2(accB, c2, c3);
    *(float4*)(out + ((size_t)b * LQ + q) * EMB + h * HD + 4 * l) =
        make_float4(c0, c1, c2, c3);
}

// ================= launch =================
extern "C" void kernel_launch(void* const* d_in, const int* in_sizes, int n_in,
                              void* d_out, int out_size) {
    const float* query  = (const float*)d_in[0];
    const float* refpts = (const float*)d_in[1];
    const float* value  = (const float*)d_in[2];
    const float* W_off  = (const float*)d_in[4];
    const float* b_off  = (const float*)d_in[5];
    const float* W_attn = (const float*)d_in[6];
    const float* b_attn = (const float*)d_in[7];
    float* out = (float*)d_out;

    dim3 tgrid((TOTAL + 63) / 64, BS * NH);
    k_transpose<<<tgrid, 256>>>(value);

    k_proj<<<MROWS / 32, 384>>>(query, refpts, W_off, b_off, W_attn, b_attn);

    int nwarps = BS * NH * QQUADS;            // 19200
    k_sample<<<(nwarps + 7) / 8, 256>>>(out);
}

// round 6
// speedup vs baseline: 1.3139x; 1.0380x over previous
#include <cuda_runtime.h>
#include <cuda_fp16.h>
#include <math.h>

// ---------------- problem constants ----------------
#define BS    32
#define LQ    300
#define NH    8
#define HD    32
#define EMB   (NH*HD)        // 256
#define NLVL  4
#define NPTS  4
#define SUMP  (NLVL*NPTS)    // 16
#define TOTAL 8500
#define MROWS (BS*LQ)        // 9600
#define NPOINT ((size_t)BS*NH*LQ*SUMP)   // 1,228,800

__device__ __constant__ int c_lvl_start[NLVL] = {0, 6400, 8000, 8400};
__device__ __constant__ int c_lvl_H[NLVL]     = {80, 40, 20, 10};
__device__ __constant__ int c_lvl_W[NLVL]     = {80, 40, 20, 10};

// ---------------- scratch ----------------
__device__ __half   g_valueT[(size_t)BS*NH*TOTAL*HD]; // ~139 MB, [b,h,s,d] fp16
__device__ ushort4  g_midx[NPOINT];                   // [bh][q][p] 4 clamped tap indices (16-bit)
__device__ float4   g_mw[NPOINT];                     // [bh][q][p] 4 attn-premult bilinear weights

// ---------------- f32x2 packed helpers (sm_103a) ----------------
typedef unsigned long long ull;
__device__ __forceinline__ ull pack2(float lo, float hi) {
    ull r; asm("mov.b64 %0, {%1, %2};" : "=l"(r) : "f"(lo), "f"(hi)); return r;
}
__device__ __forceinline__ void unpack2(ull v, float& lo, float& hi) {
    asm("mov.b64 {%0, %1}, %2;" : "=f"(lo), "=f"(hi) : "l"(v));
}
__device__ __forceinline__ void ffma2(ull& d, ull a, ull b) {
    asm("fma.rn.f32x2 %0, %1, %2, %0;" : "+l"(d) : "l"(a), "l"(b));
}
__device__ __forceinline__ void fadd2(ull& d, ull a) {
    asm("add.rn.f32x2 %0, %0, %1;" : "+l"(d) : "l"(a));
}

// ================= kernel 1: value transpose fp32 [b,h,d,s] -> fp16 [b,h,s,d] =================
__global__ __launch_bounds__(256) void k_transpose(const float* __restrict__ value) {
    __shared__ float tile[32 * 68];
    int bh = blockIdx.y;
    int s0 = blockIdx.x * 64;
    int t  = threadIdx.x;
    int sx4 = t & 15;
    int dh  = t >> 4;

    const float* src = value + (size_t)bh * HD * TOTAL;
    __half* dst = g_valueT + (size_t)bh * TOTAL * HD;

    int sbase = s0 + sx4 * 4;
    #pragma unroll
    for (int i = 0; i < 2; i++) {
        int d = dh + i * 16;
        float4 v;
        if (sbase + 3 < TOTAL) {
            v = *(const float4*)(src + (size_t)d * TOTAL + sbase);
        } else {
            v.x = (sbase + 0 < TOTAL) ? src[(size_t)d * TOTAL + sbase + 0] : 0.f;
            v.y = (sbase + 1 < TOTAL) ? src[(size_t)d * TOTAL + sbase + 1] : 0.f;
            v.z = (sbase + 2 < TOTAL) ? src[(size_t)d * TOTAL + sbase + 2] : 0.f;
            v.w = (sbase + 3 < TOTAL) ? src[(size_t)d * TOTAL + sbase + 3] : 0.f;
        }
        *(float4*)(tile + d * 68 + sx4 * 4) = v;
    }
    __syncthreads();
    #pragma unroll
    for (int i = 0; i < 4; i++) {
        int e  = t + i * 256;
        int r  = e >> 4;
        int dp = e & 15;
        int s  = s0 + r;
        if (s < TOTAL) {
            float lo = tile[(2*dp)     * 68 + r];
            float hi = tile[(2*dp + 1) * 68 + r];
            *((__half2*)(dst + (size_t)s * HD) + dp) = __floats2half2_rn(lo, hi);
        }
    }
}

// ================= kernel 2: fused projections + softmax + tap meta (attn premult) =================
// Block = 32 query rows, 384 threads. rt = t/96 -> rows rt*8..+7; ct = t%96 -> cols 4ct..4ct+3
// of the virtual [W_off | W_attn] matrix. Warps are uniform in matrix type.
__global__ __launch_bounds__(384, 2) void k_proj(const float* __restrict__ query,
                                                 const float* __restrict__ refpts,
                                                 const float* __restrict__ W_off,
                                                 const float* __restrict__ b_off,
                                                 const float* __restrict__ W_attn,
                                                 const float* __restrict__ b_attn) {
    __shared__ float qs[EMB * 34];       // [k][row]
    __shared__ float attn_s[32 * 128];   // [row][h*16+p]
    int m0 = blockIdx.x * 32;
    int t  = threadIdx.x;

    for (int idx = t; idx < 32 * EMB; idx += 384) {
        int row = idx >> 8;
        int k   = idx & 255;
        qs[k * 34 + row] = query[(size_t)m0 * EMB + idx];
    }
    __syncthreads();

    int rt = t / 96;                     // 0..3
    int ct = t % 96;                     // 0..95
    bool is_off = (ct < 64);

    const float* Wp;
    int ldw;
    if (is_off) { Wp = W_off  + 4 * ct;        ldw = EMB; }
    else        { Wp = W_attn + 4 * (ct - 64); ldw = NH * SUMP; }

    ull acc[4][4];
    #pragma unroll
    for (int j = 0; j < 4; j++)
        #pragma unroll
        for (int c = 0; c < 4; c++) acc[j][c] = 0ull;

    #pragma unroll 2
    for (int k = 0; k < EMB; k++) {
        ull q2[4];
        #pragma unroll
        for (int j = 0; j < 4; j++)
            q2[j] = *(const ull*)(qs + k * 34 + rt * 8 + 2 * j);
        float4 w = *(const float4*)(Wp + (size_t)k * ldw);
        ull w2[4];
        w2[0] = pack2(w.x, w.x); w2[1] = pack2(w.y, w.y);
        w2[2] = pack2(w.z, w.z); w2[3] = pack2(w.w, w.w);
        #pragma unroll
        for (int c = 0; c < 4; c++)
            #pragma unroll
            for (int j = 0; j < 4; j++)
                ffma2(acc[j][c], q2[j], w2[c]);
    }

    float bias_[4];
    {
        const float* bp = is_off ? (b_off + 4 * ct) : (b_attn + 4 * (ct - 64));
        float4 bb = *(const float4*)bp;
        bias_[0] = bb.x; bias_[1] = bb.y; bias_[2] = bb.z; bias_[3] = bb.w;
    }

    // ---- phase A: attn threads -> softmax -> smem ----
    if (!is_off) {
        int cta = ct - 64;
        int h   = cta >> 2;
        int p0  = (4 * cta) & 15;
        #pragma unroll
        for (int j = 0; j < 4; j++) {
            #pragma unroll
            for (int par = 0; par < 2; par++) {
                int r  = rt * 8 + 2 * j + par;
                float v[4];
                float mx = -1e30f;
                #pragma unroll
                for (int c = 0; c < 4; c++) {
                    float lo, hi; unpack2(acc[j][c], lo, hi);
                    v[c] = (par ? hi : lo) + bias_[c];
                    mx = fmaxf(mx, v[c]);
                }
                mx = fmaxf(mx, __shfl_xor_sync(0xffffffffu, mx, 1));
                mx = fmaxf(mx, __shfl_xor_sync(0xffffffffu, mx, 2));
                float s = 0.f;
                #pragma unroll
                for (int c = 0; c < 4; c++) { v[c] = __expf(v[c] - mx); s += v[c]; }
                s += __shfl_xor_sync(0xffffffffu, s, 1);
                s += __shfl_xor_sync(0xffffffffu, s, 2);
                float inv = __frcp_rn(s);
                #pragma unroll
                for (int c = 0; c < 4; c++)
                    attn_s[r * 128 + h * 16 + p0 + c] = v[c] * inv;
            }
        }
    }
    __syncthreads();

    // ---- phase B: off threads -> locations -> tap meta (attn-premultiplied) ----
    if (is_off) {
        int h     = ct >> 3;
        int pbase = (2 * ct) & 15;
        int lvl   = pbase >> 2;
        int Hh = c_lvl_H[lvl], Ww = c_lvl_W[lvl];
        int st = c_lvl_start[lvl];

        #pragma unroll
        for (int j = 0; j < 4; j++) {
            #pragma unroll
            for (int par = 0; par < 2; par++) {
                int r  = rt * 8 + 2 * j + par;
                int gm = m0 + r;
                int b  = gm / LQ;
                int q  = gm - b * LQ;
                float4 rp = __ldg((const float4*)refpts + gm);
                size_t obase = ((size_t)(b * NH + h) * LQ + q) * SUMP + pbase;
                #pragma unroll
                for (int pt = 0; pt < 2; pt++) {
                    float lo0, hi0, lo1, hi1;
                    unpack2(acc[j][2*pt],     lo0, hi0);
                    unpack2(acc[j][2*pt + 1], lo1, hi1);
                    float vx = (par ? hi0 : lo0) + bias_[2*pt];
                    float vy = (par ? hi1 : lo1) + bias_[2*pt + 1];
                    float locx = fmaf(vx * 0.125f, rp.z, rp.x);
                    float locy = fmaf(vy * 0.125f, rp.w, rp.y);

                    float x = locx * (float)Ww - 0.5f;
                    float y = locy * (float)Hh - 0.5f;
                    float fx0 = floorf(x), fy0 = floorf(y);
                    int ix0 = (int)fx0, iy0 = (int)fy0;
                    float fx = x - fx0, fy = y - fy0;
                    int ix1 = ix0 + 1, iy1 = iy0 + 1;

                    bool vx0 = (ix0 >= 0) & (ix0 < Ww);
                    bool vx1 = (ix1 >= 0) & (ix1 < Ww);
                    bool vy0 = (iy0 >= 0) & (iy0 < Hh);
                    bool vy1 = (iy1 >= 0) & (iy1 < Hh);

                    int cx0 = min(max(ix0, 0), Ww - 1);
                    int cx1 = min(max(ix1, 0), Ww - 1);
                    int cy0 = min(max(iy0, 0), Hh - 1);
                    int cy1 = min(max(iy1, 0), Hh - 1);

                    float a = attn_s[r * 128 + h * 16 + pbase + pt];

                    ushort4 idx;
                    idx.x = (unsigned short)(st + cy0 * Ww + cx0);
                    idx.y = (unsigned short)(st + cy0 * Ww + cx1);
                    idx.z = (unsigned short)(st + cy1 * Ww + cx0);
                    idx.w = (unsigned short)(st + cy1 * Ww + cx1);

                    float4 w4;
                    w4.x = (vx0 & vy0) ? a * (1.f - fx) * (1.f - fy) : 0.f;
                    w4.y = (vx1 & vy0) ? a * fx * (1.f - fy)         : 0.f;
                    w4.z = (vx0 & vy1) ? a * (1.f - fx) * fy         : 0.f;
                    w4.w = (vx1 & vy1) ? a * fx * fy                 : 0.f;

                    g_midx[obase + pt] = idx;
                    g_mw[obase + pt]   = w4;
                }
            }
        }
    }
}

// ================= kernel 3: bilinear sampling + weighted sum =================
// Warp = 8 queries; 4 lanes per query; lane = 8 channels (LDG.128 taps).
#define QOCT ((LQ + 7) / 8)   // 38
__global__ __launch_bounds__(256) void k_sample(float* __restrict__ out) {
    int wq = blockIdx.x * 8 + (threadIdx.x >> 5);   // < 256*38 = 9728
    int lane = threadIdx.x & 31;
    int qi = lane >> 2;       // query sub-index in octet
    int l  = lane & 3;        // channel octet index (channels 8l..8l+7)

    int oct = wq % QOCT;
    int bh  = wq / QOCT;
    int q   = oct * 8 + qi;
    bool valid = (q < LQ);
    int qc = valid ? q : (LQ - 1);
    int b = bh >> 3;
    int h = bh & 7;

    size_t base = ((size_t)bh * LQ + qc) * SUMP;
    const uint2*  __restrict__ mi2 = (const uint2*)(g_midx + base);
    const float4* __restrict__ mw  = g_mw + base;
    const float4* __restrict__ vt16 =
        (const float4*)(g_valueT + (size_t)bh * TOTAL * HD);  // 16B = 8 channels

    ull acc0 = 0ull, acc1 = 0ull, acc2v = 0ull, acc3 = 0ull;

    #pragma unroll
    for (int p = 0; p < SUMP; p++) {
        uint2  u = __ldg(mi2 + p);
        float4 w = __ldg(mw + p);
        int i00 = u.x & 0xFFFF;
        int i10 = u.x >> 16;
        int i01 = u.y & 0xFFFF;
        int i11 = u.y >> 16;

        __half2 z = __float2half2_rn(0.f);
        __half2 bl0 = z, bl1 = z, bl2 = z, bl3 = z;

        {
            float4 v = __ldg(vt16 + (size_t)i00 * 4 + l);
            const __half2* vh = (const __half2*)&v;
            __half2 wh = __float2half2_rn(w.x);
            bl0 = __hfma2(vh[0], wh, bl0); bl1 = __hfma2(vh[1], wh, bl1);
            bl2 = __hfma2(vh[2], wh, bl2); bl3 = __hfma2(vh[3], wh, bl3);
        }
        {
            float4 v = __ldg(vt16 + (size_t)i10 * 4 + l);
            const __half2* vh = (const __half2*)&v;
            __half2 wh = __float2half2_rn(w.y);
            bl0 = __hfma2(vh[0], wh, bl0); bl1 = __hfma2(vh[1], wh, bl1);
            bl2 = __hfma2(vh[2], wh, bl2); bl3 = __hfma2(vh[3], wh, bl3);
        }
        {
            float4 v = __ldg(vt16 + (size_t)i01 * 4 + l);
            const __half2* vh = (const __half2*)&v;
            __half2 wh = __float2half2_rn(w.z);
            bl0 = __hfma2(vh[0], wh, bl0); bl1 = __hfma2(vh[1], wh, bl1);
            bl2 = __hfma2(vh[2], wh, bl2); bl3 = __hfma2(vh[3], wh, bl3);
        }
        {
            float4 v = __ldg(vt16 + (size_t)i11 * 4 + l);
            const __half2* vh = (const __half2*)&v;
            __half2 wh = __float2half2_rn(w.w);
            bl0 = __hfma2(vh[0], wh, bl0); bl1 = __hfma2(vh[1], wh, bl1);
            bl2 = __hfma2(vh[2], wh, bl2); bl3 = __hfma2(vh[3], wh, bl3);
        }

        float2 f0 = __half22float2(bl0);
        float2 f1 = __half22float2(bl1);
        float2 f2 = __half22float2(bl2);
        float2 f3 = __half22float2(bl3);
        fadd2(acc0, pack2(f0.x, f0.y));
        fadd2(acc1, pack2(f1.x, f1.y));
        fadd2(acc2v, pack2(f2.x, f2.y));
        fadd2(acc3, pack2(f3.x, f3.y));
    }

    if (valid) {
        float o0,o1,o2,o3,o4,o5,o6,o7;
        unpack2(acc0, o0, o1);
        unpack2(acc1, o2, o3);
        unpack2(acc2v, o4, o5);
        unpack2(acc3, o6, o7);
        float* op = out + ((size_t)b * LQ + q) * EMB + h * HD + 8 * l;
        *(float4*)(op)     = make_float4(o0, o1, o2, o3);
        *(float4*)(op + 4) = make_float4(o4, o5, o6, o7);
    }
}

// ================= launch =================
extern "C" void kernel_launch(void* const* d_in, const int* in_sizes, int n_in,
                              void* d_out, int out_size) {
    const float* query  = (const float*)d_in[0];
    const float* refpts = (const float*)d_in[1];
    const float* value  = (const float*)d_in[2];
    const float* W_off  = (const float*)d_in[4];
    const float* b_off  = (const float*)d_in[5];
    const float* W_attn = (const float*)d_in[6];
    const float* b_attn = (const float*)d_in[7];
    float* out = (float*)d_out;

    dim3 tgrid((TOTAL + 63) / 64, BS * NH);
    k_transpose<<<tgrid, 256>>>(value);

    k_proj<<<MROWS / 32, 384>>>(query, refpts, W_off, b_off, W_attn, b_attn);

    int nwarps = BS * NH * QOCT;              // 9728
    k_sample<<<(nwarps + 7) / 8, 256>>>(out);
}

// round 7
// speedup vs baseline: 1.4189x; 1.0799x over previous
#include <cuda_runtime.h>
#include <cuda_fp16.h>
#include <math.h>

// ---------------- problem constants ----------------
#define BS    32
#define LQ    300
#define NH    8
#define HD    32
#define EMB   (NH*HD)        // 256
#define NLVL  4
#define NPTS  4
#define SUMP  (NLVL*NPTS)    // 16
#define TOTAL 8500
#define MROWS (BS*LQ)        // 9600
#define NPOINT ((size_t)BS*NH*LQ*SUMP)   // 1,228,800

__device__ __constant__ int c_lvl_start[NLVL] = {0, 6400, 8000, 8400};
__device__ __constant__ int c_lvl_H[NLVL]     = {80, 40, 20, 10};
__device__ __constant__ int c_lvl_W[NLVL]     = {80, 40, 20, 10};

// ---------------- scratch ----------------
__device__ __half   g_valueT[(size_t)BS*NH*TOTAL*HD]; // ~139 MB, [b,h,s,d] fp16
__device__ ushort4  g_midx[NPOINT];                   // [bh][q][p] 4 clamped tap indices (16-bit)
__device__ float4   g_mw[NPOINT];                     // [bh][q][p] 4 attn-premult bilinear weights

// ---------------- f32x2 packed helpers (sm_103a) ----------------
typedef unsigned long long ull;
__device__ __forceinline__ ull pack2(float lo, float hi) {
    ull r; asm("mov.b64 %0, {%1, %2};" : "=l"(r) : "f"(lo), "f"(hi)); return r;
}
__device__ __forceinline__ void unpack2(ull v, float& lo, float& hi) {
    asm("mov.b64 {%0, %1}, %2;" : "=f"(lo), "=f"(hi) : "l"(v));
}
__device__ __forceinline__ void ffma2(ull& d, ull a, ull b) {
    asm("fma.rn.f32x2 %0, %1, %2, %0;" : "+l"(d) : "l"(a), "l"(b));
}
__device__ __forceinline__ void fadd2(ull& d, ull a) {
    asm("add.rn.f32x2 %0, %0, %1;" : "+l"(d) : "l"(a));
}

// ================= kernel 1: value transpose fp32 [b,h,d,s] -> fp16 [b,h,s,d] =================
__global__ __launch_bounds__(256) void k_transpose(const float* __restrict__ value) {
    __shared__ float tile[32 * 68];
    int bh = blockIdx.y;
    int s0 = blockIdx.x * 64;
    int t  = threadIdx.x;
    int sx4 = t & 15;
    int dh  = t >> 4;

    const float* src = value + (size_t)bh * HD * TOTAL;
    __half* dst = g_valueT + (size_t)bh * TOTAL * HD;

    int sbase = s0 + sx4 * 4;
    #pragma unroll
    for (int i = 0; i < 2; i++) {
        int d = dh + i * 16;
        float4 v;
        if (sbase + 3 < TOTAL) {
            v = *(const float4*)(src + (size_t)d * TOTAL + sbase);
        } else {
            v.x = (sbase + 0 < TOTAL) ? src[(size_t)d * TOTAL + sbase + 0] : 0.f;
            v.y = (sbase + 1 < TOTAL) ? src[(size_t)d * TOTAL + sbase + 1] : 0.f;
            v.z = (sbase + 2 < TOTAL) ? src[(size_t)d * TOTAL + sbase + 2] : 0.f;
            v.w = (sbase + 3 < TOTAL) ? src[(size_t)d * TOTAL + sbase + 3] : 0.f;
        }
        *(float4*)(tile + d * 68 + sx4 * 4) = v;
    }
    __syncthreads();
    #pragma unroll
    for (int i = 0; i < 4; i++) {
        int e  = t + i * 256;
        int r  = e >> 4;
        int dp = e & 15;
        int s  = s0 + r;
        if (s < TOTAL) {
            float lo = tile[(2*dp)     * 68 + r];
            float hi = tile[(2*dp + 1) * 68 + r];
            *((__half2*)(dst + (size_t)s * HD) + dp) = __floats2half2_rn(lo, hi);
        }
    }
}

// ================= kernel 2: fused projections + softmax + tap meta (attn premult) =================
// Block = 16 query rows, 192 threads (600 blocks -> single wave at occ>=5).
// rt = t/96 (0..1) -> rows rt*8..+7; ct = t%96 -> cols 4ct..4ct+3 of virtual [W_off|W_attn].
__global__ __launch_bounds__(192) void k_proj(const float* __restrict__ query,
                                              const float* __restrict__ refpts,
                                              const float* __restrict__ W_off,
                                              const float* __restrict__ b_off,
                                              const float* __restrict__ W_attn,
                                              const float* __restrict__ b_attn) {
    __shared__ float qs[EMB * 18];       // [k][row], stride 18 (even => 8B-aligned pairs)
    __shared__ float attn_s[16 * 128];   // [row][h*16+p]
    int m0 = blockIdx.x * 16;
    int t  = threadIdx.x;

    for (int idx = t; idx < 16 * EMB; idx += 192) {
        int row = idx >> 8;
        int k   = idx & 255;
        qs[k * 18 + row] = query[(size_t)m0 * EMB + idx];
    }
    __syncthreads();

    int rt = t / 96;                     // 0..1
    int ct = t % 96;                     // 0..95
    bool is_off = (ct < 64);

    const float* Wp;
    int ldw;
    if (is_off) { Wp = W_off  + 4 * ct;        ldw = EMB; }
    else        { Wp = W_attn + 4 * (ct - 64); ldw = NH * SUMP; }

    ull acc[4][4];
    #pragma unroll
    for (int j = 0; j < 4; j++)
        #pragma unroll
        for (int c = 0; c < 4; c++) acc[j][c] = 0ull;

    #pragma unroll 2
    for (int k = 0; k < EMB; k++) {
        ull q2[4];
        #pragma unroll
        for (int j = 0; j < 4; j++)
            q2[j] = *(const ull*)(qs + k * 18 + rt * 8 + 2 * j);
        float4 w = *(const float4*)(Wp + (size_t)k * ldw);
        ull w2[4];
        w2[0] = pack2(w.x, w.x); w2[1] = pack2(w.y, w.y);
        w2[2] = pack2(w.z, w.z); w2[3] = pack2(w.w, w.w);
        #pragma unroll
        for (int c = 0; c < 4; c++)
            #pragma unroll
            for (int j = 0; j < 4; j++)
                ffma2(acc[j][c], q2[j], w2[c]);
    }

    float bias_[4];
    {
        const float* bp = is_off ? (b_off + 4 * ct) : (b_attn + 4 * (ct - 64));
        float4 bb = *(const float4*)bp;
        bias_[0] = bb.x; bias_[1] = bb.y; bias_[2] = bb.z; bias_[3] = bb.w;
    }

    // ---- phase A: attn threads -> softmax -> smem ----
    if (!is_off) {
        int cta = ct - 64;
        int h   = cta >> 2;
        int p0  = (4 * cta) & 15;
        #pragma unroll
        for (int j = 0; j < 4; j++) {
            #pragma unroll
            for (int par = 0; par < 2; par++) {
                int r  = rt * 8 + 2 * j + par;
                float v[4];
                float mx = -1e30f;
                #pragma unroll
                for (int c = 0; c < 4; c++) {
                    float lo, hi; unpack2(acc[j][c], lo, hi);
                    v[c] = (par ? hi : lo) + bias_[c];
                    mx = fmaxf(mx, v[c]);
                }
                mx = fmaxf(mx, __shfl_xor_sync(0xffffffffu, mx, 1));
                mx = fmaxf(mx, __shfl_xor_sync(0xffffffffu, mx, 2));
                float s = 0.f;
                #pragma unroll
                for (int c = 0; c < 4; c++) { v[c] = __expf(v[c] - mx); s += v[c]; }
                s += __shfl_xor_sync(0xffffffffu, s, 1);
                s += __shfl_xor_sync(0xffffffffu, s, 2);
                float inv = __frcp_rn(s);
                #pragma unroll
                for (int c = 0; c < 4; c++)
                    attn_s[r * 128 + h * 16 + p0 + c] = v[c] * inv;
            }
        }
    }
    __syncthreads();

    // ---- phase B: off threads -> locations -> tap meta (attn-premultiplied) ----
    if (is_off) {
        int h     = ct >> 3;
        int pbase = (2 * ct) & 15;
        int lvl   = pbase >> 2;
        int Hh = c_lvl_H[lvl], Ww = c_lvl_W[lvl];
        int st = c_lvl_start[lvl];

        #pragma unroll
        for (int j = 0; j < 4; j++) {
            #pragma unroll
            for (int par = 0; par < 2; par++) {
                int r  = rt * 8 + 2 * j + par;
                int gm = m0 + r;
                int b  = gm / LQ;
                int q  = gm - b * LQ;
                float4 rp = __ldg((const float4*)refpts + gm);
                size_t obase = ((size_t)(b * NH + h) * LQ + q) * SUMP + pbase;
                #pragma unroll
                for (int pt = 0; pt < 2; pt++) {
                    float lo0, hi0, lo1, hi1;
                    unpack2(acc[j][2*pt],     lo0, hi0);
                    unpack2(acc[j][2*pt + 1], lo1, hi1);
                    float vx = (par ? hi0 : lo0) + bias_[2*pt];
                    float vy = (par ? hi1 : lo1) + bias_[2*pt + 1];
                    float locx = fmaf(vx * 0.125f, rp.z, rp.x);
                    float locy = fmaf(vy * 0.125f, rp.w, rp.y);

                    float x = locx * (float)Ww - 0.5f;
                    float y = locy * (float)Hh - 0.5f;
                    float fx0 = floorf(x), fy0 = floorf(y);
                    int ix0 = (int)fx0, iy0 = (int)fy0;
                    float fx = x - fx0, fy = y - fy0;
                    int ix1 = ix0 + 1, iy1 = iy0 + 1;

                    bool vx0 = (ix0 >= 0) & (ix0 < Ww);
                    bool vx1 = (ix1 >= 0) & (ix1 < Ww);
                    bool vy0 = (iy0 >= 0) & (iy0 < Hh);
                    bool vy1 = (iy1 >= 0) & (iy1 < Hh);

                    int cx0 = min(max(ix0, 0), Ww - 1);
                    int cx1 = min(max(ix1, 0), Ww - 1);
                    int cy0 = min(max(iy0, 0), Hh - 1);
                    int cy1 = min(max(iy1, 0), Hh - 1);

                    float a = attn_s[r * 128 + h * 16 + pbase + pt];

                    ushort4 idx;
                    idx.x = (unsigned short)(st + cy0 * Ww + cx0);
                    idx.y = (unsigned short)(st + cy0 * Ww + cx1);
                    idx.z = (unsigned short)(st + cy1 * Ww + cx0);
                    idx.w = (unsigned short)(st + cy1 * Ww + cx1);

                    float4 w4;
                    w4.x = (vx0 & vy0) ? a * (1.f - fx) * (1.f - fy) : 0.f;
                    w4.y = (vx1 & vy0) ? a * fx * (1.f - fy)         : 0.f;
                    w4.z = (vx0 & vy1) ? a * (1.f - fx) * fy         : 0.f;
                    w4.w = (vx1 & vy1) ? a * fx * fy                 : 0.f;

                    g_midx[obase + pt] = idx;
                    g_mw[obase + pt]   = w4;
                }
            }
        }
    }
}

// ================= kernel 3: bilinear sampling + weighted sum =================
// Warp = 8 queries; 4 lanes per query; lane = 8 channels (LDG.128 taps).
#define QOCT ((LQ + 7) / 8)   // 38
__global__ __launch_bounds__(256) void k_sample(float* __restrict__ out) {
    int wq = blockIdx.x * 8 + (threadIdx.x >> 5);   // < 256*38 = 9728
    int lane = threadIdx.x & 31;
    int qi = lane >> 2;       // query sub-index in octet
    int l  = lane & 3;        // channel octet index (channels 8l..8l+7)

    int oct = wq % QOCT;
    int bh  = wq / QOCT;
    int q   = oct * 8 + qi;
    bool valid = (q < LQ);
    int qc = valid ? q : (LQ - 1);
    int b = bh >> 3;
    int h = bh & 7;

    size_t base = ((size_t)bh * LQ + qc) * SUMP;
    const uint2*  __restrict__ mi2 = (const uint2*)(g_midx + base);
    const float4* __restrict__ mw  = g_mw + base;
    const float4* __restrict__ vt16 =
        (const float4*)(g_valueT + (size_t)bh * TOTAL * HD);  // 16B = 8 channels

    ull acc0 = 0ull, acc1 = 0ull, acc2v = 0ull, acc3 = 0ull;

    #pragma unroll
    for (int p = 0; p < SUMP; p++) {
        uint2  u = __ldg(mi2 + p);
        float4 w = __ldg(mw + p);
        int i00 = u.x & 0xFFFF;
        int i10 = u.x >> 16;
        int i01 = u.y & 0xFFFF;
        int i11 = u.y >> 16;

        __half2 z = __float2half2_rn(0.f);
        __half2 bl0 = z, bl1 = z, bl2 = z, bl3 = z;

        {
            float4 v = __ldg(vt16 + (size_t)i00 * 4 + l);
            const __half2* vh = (const __half2*)&v;
            __half2 wh = __float2half2_rn(w.x);
            bl0 = __hfma2(vh[0], wh, bl0); bl1 = __hfma2(vh[1], wh, bl1);
            bl2 = __hfma2(vh[2], wh, bl2); bl3 = __hfma2(vh[3], wh, bl3);
        }
        {
            float4 v = __ldg(vt16 + (size_t)i10 * 4 + l);
            const __half2* vh = (const __half2*)&v;
            __half2 wh = __float2half2_rn(w.y);
            bl0 = __hfma2(vh[0], wh, bl0); bl1 = __hfma2(vh[1], wh, bl1);
            bl2 = __hfma2(vh[2], wh, bl2); bl3 = __hfma2(vh[3], wh, bl3);
        }
        {
            float4 v = __ldg(vt16 + (size_t)i01 * 4 + l);
            const __half2* vh = (const __half2*)&v;
            __half2 wh = __float2half2_rn(w.z);
            bl0 = __hfma2(vh[0], wh, bl0); bl1 = __hfma2(vh[1], wh, bl1);
            bl2 = __hfma2(vh[2], wh, bl2); bl3 = __hfma2(vh[3], wh, bl3);
        }
        {
            float4 v = __ldg(vt16 + (size_t)i11 * 4 + l);
            const __half2* vh = (const __half2*)&v;
            __half2 wh = __float2half2_rn(w.w);
            bl0 = __hfma2(vh[0], wh, bl0); bl1 = __hfma2(vh[1], wh, bl1);
            bl2 = __hfma2(vh[2], wh, bl2); bl3 = __hfma2(vh[3], wh, bl3);
        }

        float2 f0 = __half22float2(bl0);
        float2 f1 = __half22float2(bl1);
        float2 f2 = __half22float2(bl2);
        float2 f3 = __half22float2(bl3);
        fadd2(acc0, pack2(f0.x, f0.y));
        fadd2(acc1, pack2(f1.x, f1.y));
        fadd2(acc2v, pack2(f2.x, f2.y));
        fadd2(acc3, pack2(f3.x, f3.y));
    }

    if (valid) {
        float o0,o1,o2,o3,o4,o5,o6,o7;
        unpack2(acc0, o0, o1);
        unpack2(acc1, o2, o3);
        unpack2(acc2v, o4, o5);
        unpack2(acc3, o6, o7);
        float* op = out + ((size_t)b * LQ + q) * EMB + h * HD + 8 * l;
        *(float4*)(op)     = make_float4(o0, o1, o2, o3);
        *(float4*)(op + 4) = make_float4(o4, o5, o6, o7);
    }
}

// ================= launch =================
// Fork proj onto a side stream so it overlaps the DRAM-bound transpose:
//   { transpose || proj } -> sample
// Stream/events are host objects (no device allocation). They are leaked
// intentionally: destroying a stream that participated in an active capture
// would invalidate the capture, and kernel_launch is only invoked twice.
extern "C" void kernel_launch(void* const* d_in, const int* in_sizes, int n_in,
                              void* d_out, int out_size) {
    const float* query  = (const float*)d_in[0];
    const float* refpts = (const float*)d_in[1];
    const float* value  = (const float*)d_in[2];
    const float* W_off  = (const float*)d_in[4];
    const float* b_off  = (const float*)d_in[5];
    const float* W_attn = (const float*)d_in[6];
    const float* b_attn = (const float*)d_in[7];
    float* out = (float*)d_out;

    cudaStream_t s2;
    cudaEvent_t eFork, eJoin;
    cudaStreamCreateWithFlags(&s2, cudaStreamNonBlocking);
    cudaEventCreateWithFlags(&eFork, cudaEventDisableTiming);
    cudaEventCreateWithFlags(&eJoin, cudaEventDisableTiming);

    // fork: s2 joins the (possibly capturing) main stream's dependency graph
    cudaEventRecord(eFork, 0);
    cudaStreamWaitEvent(s2, eFork, 0);

    // side stream: projections + softmax + tap meta (compute-bound)
    k_proj<<<MROWS / 16, 192, 0, s2>>>(query, refpts, W_off, b_off, W_attn, b_attn);
    cudaEventRecord(eJoin, s2);

    // main stream: value transpose (DRAM-bound)
    dim3 tgrid((TOTAL + 63) / 64, BS * NH);
    k_transpose<<<tgrid, 256>>>(value);

    // join, then sample
    cudaStreamWaitEvent(0, eJoin, 0);
    int nwarps = BS * NH * QOCT;              // 9728
    k_sample<<<(nwarps + 7) / 8, 256>>>(out);
}